// round 1
// baseline (speedup 1.0000x reference)
#include <cuda_runtime.h>
#include <math_constants.h>

#define B    32
#define T    336
#define C    7
#define NSH  5
#define NG   4
#define NF   140            // 4 groups * 5 * 7
#define OUTC 10

// offsets in d_out (floats): out[320] | dists[4480] | probs[4480] | loss[1]
#define OFF_OUT   0
#define OFF_DIST  320
#define OFF_PROB  (320 + B*NF)
#define OFF_LOSS  (320 + 2*B*NF)

__device__ float g_xn[B * C * T];   // normalized, (b,c) rows contiguous in t

// ---------------------------------------------------------------------------
// Kernel 1: per-(b,c) normalization over t with ddof=1 std
// ---------------------------------------------------------------------------
__global__ void norm_kernel(const float* __restrict__ x) {
    const int bc = blockIdx.x;            // b*C + ch
    const int b  = bc / C;
    const int ch = bc % C;
    const float* xrow = x + (size_t)b * T * C + ch;   // stride C over t

    __shared__ float red[4];
    const int tid = threadIdx.x;          // 128 threads

    float vals[3];
    float s = 0.f;
    #pragma unroll
    for (int i = 0; i < 3; i++) {
        int t = tid + i * 128;
        vals[i] = (t < T) ? xrow[(size_t)t * C] : 0.f;
        s += vals[i];
    }
    #pragma unroll
    for (int o = 16; o > 0; o >>= 1) s += __shfl_xor_sync(0xffffffffu, s, o);
    if ((tid & 31) == 0) red[tid >> 5] = s;
    __syncthreads();
    const float mu = (red[0] + red[1] + red[2] + red[3]) / (float)T;

    float ss = 0.f;
    #pragma unroll
    for (int i = 0; i < 3; i++) {
        int t = tid + i * 128;
        if (t < T) { float d = vals[i] - mu; ss += d * d; }
    }
    #pragma unroll
    for (int o = 16; o > 0; o >>= 1) ss += __shfl_xor_sync(0xffffffffu, ss, o);
    __syncthreads();
    if ((tid & 31) == 0) red[tid >> 5] = ss;
    __syncthreads();
    const float sstot = red[0] + red[1] + red[2] + red[3];
    const float sd    = sqrtf(sstot / (float)(T - 1));
    const float inv   = 1.f / (sd + 1e-8f);

    float* out = g_xn + (size_t)bc * T;
    #pragma unroll
    for (int i = 0; i < 3; i++) {
        int t = tid + i * 128;
        if (t < T) out[t] = (vals[i] - mu) * inv;
    }
}

// ---------------------------------------------------------------------------
// Kernel 2: sliding-window min L1 distance per (b, ch, group, shapelet)
// grid = (B*C, 4 groups), 128 threads, K=4 rolling windows per thread
// ---------------------------------------------------------------------------
__global__ void shapelet_kernel(const float* __restrict__ w0,
                                const float* __restrict__ w1,
                                const float* __restrict__ w2,
                                const float* __restrict__ w3,
                                float* __restrict__ d_out) {
    const int g  = blockIdx.y;
    const int bc = blockIdx.x;            // b*C + ch
    const int b  = bc / C;
    const int ch = bc % C;

    int L;
    const float* wg;
    switch (g) {
        case 0: L = 34;  wg = w0; break;
        case 1: L = 68;  wg = w1; break;
        case 2: L = 101; wg = w2; break;
        default: L = 168; wg = w3; break;
    }
    const int tw = T - L + 1;

    __shared__ float sx[T + 8];           // padded for rolling-buffer overread
    __shared__ float sw[NSH * 168];
    __shared__ float rmin[4];

    const int tid = threadIdx.x;          // 128

    for (int t = tid; t < T + 8; t += 128)
        sx[t] = (t < T) ? g_xn[(size_t)bc * T + t] : 0.f;
    for (int i = tid; i < NSH * L; i += 128) {
        int nn = i / L, l = i % L;
        sw[i] = wg[(size_t)(nn * C + ch) * L + l];
    }
    __syncthreads();

    float* dists = d_out + OFF_DIST;
    float* probs = d_out + OFF_PROB;

    for (int nn = 0; nn < NSH; nn++) {
        const float* swn = sw + nn * L;
        const int j0 = tid * 4;
        float m = CUDART_INF_F;

        if (j0 < tw) {
            float a0 = 0.f, a1 = 0.f, a2 = 0.f, a3 = 0.f;
            float r0 = sx[j0], r1 = sx[j0 + 1], r2 = sx[j0 + 2], r3 = sx[j0 + 3];
            #pragma unroll 4
            for (int l = 0; l < L; l++) {
                float r4 = sx[j0 + 4 + l];     // one new value / step
                float wv = swn[l];             // broadcast
                a0 += fabsf(r0 - wv);
                a1 += fabsf(r1 - wv);
                a2 += fabsf(r2 - wv);
                a3 += fabsf(r3 - wv);
                r0 = r1; r1 = r2; r2 = r3; r3 = r4;
            }
            m = a0;
            if (j0 + 1 < tw) m = fminf(m, a1);
            if (j0 + 2 < tw) m = fminf(m, a2);
            if (j0 + 3 < tw) m = fminf(m, a3);
        }

        #pragma unroll
        for (int o = 16; o > 0; o >>= 1)
            m = fminf(m, __shfl_xor_sync(0xffffffffu, m, o));
        if ((tid & 31) == 0) rmin[tid >> 5] = m;
        __syncthreads();

        if (tid == 0) {
            float mm   = fminf(fminf(rmin[0], rmin[1]), fminf(rmin[2], rmin[3]));
            float dmin = mm / (float)L;
            int   idx  = b * NF + g * (NSH * C) + nn * C + ch;
            dists[idx] = dmin;
            probs[idx] = expf(-dmin * dmin);   // EPS_GATE = 1
        }
        __syncthreads();
    }
}

// ---------------------------------------------------------------------------
// Kernel 3: out = probs @ W_out^T  and  loss = 0.1 * mean|W_out|
// ---------------------------------------------------------------------------
__global__ void head_kernel(const float* __restrict__ Wout,
                            float* __restrict__ d_out) {
    const int tid = threadIdx.x;          // 512 threads, grid(1)
    const float* probs = d_out + OFF_PROB;

    if (tid < B * OUTC) {
        const int b = tid / OUTC;
        const int o = tid % OUTC;
        const float* p = probs + b * NF;
        const float* w = Wout + o * NF;
        float s = 0.f;
        #pragma unroll 4
        for (int f = 0; f < NF; f++) s += p[f] * w[f];
        d_out[OFF_OUT + tid] = s;
    }

    float ls = 0.f;
    for (int i = tid; i < OUTC * NF; i += 512) ls += fabsf(Wout[i]);
    #pragma unroll
    for (int o = 16; o > 0; o >>= 1) ls += __shfl_xor_sync(0xffffffffu, ls, o);
    __shared__ float sred[16];
    if ((tid & 31) == 0) sred[tid >> 5] = ls;
    __syncthreads();
    if (tid == 0) {
        float tot = 0.f;
        #pragma unroll
        for (int i = 0; i < 16; i++) tot += sred[i];
        d_out[OFF_LOSS] = 0.1f * tot / (float)(OUTC * NF);
    }
}

// ---------------------------------------------------------------------------
extern "C" void kernel_launch(void* const* d_in, const int* in_sizes, int n_in,
                              void* d_out, int out_size) {
    const float* x    = (const float*)d_in[0];
    const float* w0   = (const float*)d_in[1];
    const float* w1   = (const float*)d_in[2];
    const float* w2   = (const float*)d_in[3];
    const float* w3   = (const float*)d_in[4];
    const float* Wout = (const float*)d_in[5];
    float* out = (float*)d_out;

    norm_kernel<<<B * C, 128>>>(x);
    dim3 grid(B * C, NG);
    shapelet_kernel<<<grid, 128>>>(w0, w1, w2, w3, out);
    head_kernel<<<1, 512>>>(Wout, out);
}

// round 2
// speedup vs baseline: 1.0287x; 1.0287x over previous
#include <cuda_runtime.h>
#include <math_constants.h>

#define B    32
#define T    336
#define C    7
#define NSH  5
#define NG   4
#define NF   140            // 4 groups * 5 * 7
#define OUTC 10

// offsets in d_out (floats): out[320] | dists[4480] | probs[4480] | loss[1]
#define OFF_OUT   0
#define OFF_DIST  320
#define OFF_PROB  (320 + B*NF)
#define OFF_LOSS  (320 + 2*B*NF)

// ---------------------------------------------------------------------------
// Fused shapelet kernel.
// grid = (B*C, 20)   where blockIdx.y = g*5 + nn ; 128 threads.
// Each block:
//   1. loads its (b,ch) row of x (strided), one-pass mean/var, normalizes -> smem
//   2. loads shapelet row (nn, ch) of group g -> smem
//   3. K consecutive sliding windows per thread, rolling register buffer
//   4. block-min reduce, write dist & prob scalars
// ---------------------------------------------------------------------------

template<int L, int K>
__device__ __forceinline__ void sliding_min(const float* __restrict__ sx,
                                            const float* __restrict__ sw,
                                            int tid, float* __restrict__ rmin,
                                            float* __restrict__ out_min) {
    constexpr int TW = T - L + 1;
    const int j0 = tid * K;
    float m = CUDART_INF_F;

    if (j0 < TW) {
        float acc[K];
        float r[K + 1];
        #pragma unroll
        for (int k = 0; k < K; k++) { acc[k] = 0.f; r[k] = sx[j0 + k]; }
        r[K] = sx[j0 + K];

        #pragma unroll 4
        for (int l = 0; l < L; l++) {
            const float wv = sw[l];                 // broadcast
            #pragma unroll
            for (int k = 0; k < K; k++)
                acc[k] += fabsf(r[k] - wv);
            #pragma unroll
            for (int k = 0; k < K; k++) r[k] = r[k + 1];
            r[K] = sx[j0 + K + l + 1];              // one new value / step
        }

        m = acc[0];
        #pragma unroll
        for (int k = 1; k < K; k++)
            if (j0 + k < TW) m = fminf(m, acc[k]);
    }

    #pragma unroll
    for (int o = 16; o > 0; o >>= 1)
        m = fminf(m, __shfl_xor_sync(0xffffffffu, m, o));
    if ((tid & 31) == 0) rmin[tid >> 5] = m;
    __syncthreads();
    if (tid == 0) {
        float mm = fminf(fminf(rmin[0], rmin[1]), fminf(rmin[2], rmin[3]));
        *out_min = mm * (1.0f / (float)L);
    }
}

__global__ __launch_bounds__(128) void shapelet_kernel(
        const float* __restrict__ x,
        const float* __restrict__ w0,
        const float* __restrict__ w1,
        const float* __restrict__ w2,
        const float* __restrict__ w3,
        float* __restrict__ d_out) {
    const int bc = blockIdx.x;            // b*C + ch
    const int b  = bc / C;
    const int ch = bc % C;
    const int g  = blockIdx.y / NSH;
    const int nn = blockIdx.y % NSH;

    __shared__ __align__(16) float sx[T + 8];
    __shared__ __align__(16) float sw[168];
    __shared__ float red[8];
    __shared__ float result;

    const int tid = threadIdx.x;          // 128

    // ---- inline normalization (one pass: sum + sumsq) ----
    const float* xrow = x + (size_t)b * T * C + ch;   // stride C over t
    float vals[3];
    float s = 0.f, ss = 0.f;
    #pragma unroll
    for (int i = 0; i < 3; i++) {
        int t = tid + i * 128;
        float v = (t < T) ? xrow[(size_t)t * C] : 0.f;
        vals[i] = v;
        s += v;
        ss += v * v;
    }
    #pragma unroll
    for (int o = 16; o > 0; o >>= 1) {
        s  += __shfl_xor_sync(0xffffffffu, s, o);
        ss += __shfl_xor_sync(0xffffffffu, ss, o);
    }
    if ((tid & 31) == 0) { red[tid >> 5] = s; red[4 + (tid >> 5)] = ss; }
    __syncthreads();
    const float stot  = red[0] + red[1] + red[2] + red[3];
    const float sstot = red[4] + red[5] + red[6] + red[7];
    const float mu  = stot * (1.0f / (float)T);
    const float var = (sstot - (float)T * mu * mu) * (1.0f / (float)(T - 1));
    const float inv = 1.0f / (sqrtf(fmaxf(var, 0.f)) + 1e-8f);

    #pragma unroll
    for (int i = 0; i < 3; i++) {
        int t = tid + i * 128;
        if (t < T) sx[t] = (vals[i] - mu) * inv;
    }
    // pad tail so rolling buffer can overread
    if (tid < 8) sx[T + tid] = 0.f;

    // ---- load the single shapelet row (nn, ch) of group g ----
    const float* wg;
    int L;
    switch (g) {
        case 0:  L = 34;  wg = w0; break;
        case 1:  L = 68;  wg = w1; break;
        case 2:  L = 101; wg = w2; break;
        default: L = 168; wg = w3; break;
    }
    const float* wrow = wg + (size_t)(nn * C + ch) * L;
    for (int i = tid; i < L; i += 128) sw[i] = wrow[i];
    __syncthreads();

    // ---- sliding window min-L1 ----
    switch (g) {
        case 0:  sliding_min<34, 3>(sx, sw, tid, red, &result); break;   // tw=303
        case 1:  sliding_min<68, 3>(sx, sw, tid, red, &result); break;   // tw=269
        case 2:  sliding_min<101, 2>(sx, sw, tid, red, &result); break;  // tw=236
        default: sliding_min<168, 2>(sx, sw, tid, red, &result); break;  // tw=169
    }
    __syncthreads();

    if (tid == 0) {
        const float dmin = result;
        const int idx = b * NF + g * (NSH * C) + nn * C + ch;
        d_out[OFF_DIST + idx] = dmin;
        d_out[OFF_PROB + idx] = expf(-dmin * dmin);   // EPS_GATE = 1
    }
}

// ---------------------------------------------------------------------------
// Head: out = probs @ W_out^T  and  loss = 0.1 * mean|W_out|
// ---------------------------------------------------------------------------
__global__ __launch_bounds__(512) void head_kernel(const float* __restrict__ Wout,
                                                   float* __restrict__ d_out) {
    const int tid = threadIdx.x;          // 512 threads, grid(1)
    const float* probs = d_out + OFF_PROB;

    if (tid < B * OUTC) {
        const int b = tid / OUTC;
        const int o = tid % OUTC;
        const float* p = probs + b * NF;
        const float* w = Wout + o * NF;
        float s = 0.f;
        #pragma unroll 4
        for (int f = 0; f < NF; f++) s += p[f] * w[f];
        d_out[OFF_OUT + tid] = s;
    }

    float ls = 0.f;
    for (int i = tid; i < OUTC * NF; i += 512) ls += fabsf(Wout[i]);
    #pragma unroll
    for (int o = 16; o > 0; o >>= 1) ls += __shfl_xor_sync(0xffffffffu, ls, o);
    __shared__ float sred[16];
    if ((tid & 31) == 0) sred[tid >> 5] = ls;
    __syncthreads();
    if (tid == 0) {
        float tot = 0.f;
        #pragma unroll
        for (int i = 0; i < 16; i++) tot += sred[i];
        d_out[OFF_LOSS] = 0.1f * tot / (float)(OUTC * NF);
    }
}

// ---------------------------------------------------------------------------
extern "C" void kernel_launch(void* const* d_in, const int* in_sizes, int n_in,
                              void* d_out, int out_size) {
    const float* x    = (const float*)d_in[0];
    const float* w0   = (const float*)d_in[1];
    const float* w1   = (const float*)d_in[2];
    const float* w2   = (const float*)d_in[3];
    const float* w3   = (const float*)d_in[4];
    const float* Wout = (const float*)d_in[5];
    float* out = (float*)d_out;

    dim3 grid(B * C, NG * NSH);
    shapelet_kernel<<<grid, 128>>>(x, w0, w1, w2, w3, out);
    head_kernel<<<1, 512>>>(Wout, out);
}

// round 3
// speedup vs baseline: 1.6747x; 1.6280x over previous
#include <cuda_runtime.h>
#include <math_constants.h>

#define B    32
#define T    336
#define C    7
#define NSH  5
#define NG   4
#define NF   140            // 4 groups * 5 * 7
#define OUTC 10

// offsets in d_out (floats): out[320] | dists[4480] | probs[4480] | loss[1]
#define OFF_OUT   0
#define OFF_DIST  320
#define OFF_PROB  (320 + B*NF)
#define OFF_LOSS  (320 + 2*B*NF)

// ---------------------------------------------------------------------------
// Fused shapelet kernel.
// grid = (B*C, 20)   where blockIdx.y = g*5 + nn ; 128 threads.
// ---------------------------------------------------------------------------

template<int L, int K>
__device__ __forceinline__ void sliding_min(const float* __restrict__ sx,
                                            const float* __restrict__ sw,
                                            int tid, float* __restrict__ rmin,
                                            float* __restrict__ out_min) {
    constexpr int TW = T - L + 1;
    const int j0 = tid * K;
    float m = CUDART_INF_F;

    if (j0 < TW) {
        float acc[K];
        float r[K + 1];
        #pragma unroll
        for (int k = 0; k < K; k++) { acc[k] = 0.f; r[k] = sx[j0 + k]; }
        r[K] = sx[j0 + K];

        #pragma unroll 4
        for (int l = 0; l < L; l++) {
            const float wv = sw[l];                 // broadcast
            #pragma unroll
            for (int k = 0; k < K; k++)
                acc[k] += fabsf(r[k] - wv);
            #pragma unroll
            for (int k = 0; k < K; k++) r[k] = r[k + 1];
            r[K] = sx[j0 + K + l + 1];              // one new value / step
        }

        m = acc[0];
        #pragma unroll
        for (int k = 1; k < K; k++)
            if (j0 + k < TW) m = fminf(m, acc[k]);
    }

    #pragma unroll
    for (int o = 16; o > 0; o >>= 1)
        m = fminf(m, __shfl_xor_sync(0xffffffffu, m, o));
    if ((tid & 31) == 0) rmin[tid >> 5] = m;
    __syncthreads();
    if (tid == 0) {
        float mm = fminf(fminf(rmin[0], rmin[1]), fminf(rmin[2], rmin[3]));
        *out_min = mm * (1.0f / (float)L);
    }
}

__global__ __launch_bounds__(128) void shapelet_kernel(
        const float* __restrict__ x,
        const float* __restrict__ w0,
        const float* __restrict__ w1,
        const float* __restrict__ w2,
        const float* __restrict__ w3,
        float* __restrict__ d_out) {
    const int bc = blockIdx.x;            // b*C + ch
    const int b  = bc / C;
    const int ch = bc % C;
    const int g  = blockIdx.y / NSH;
    const int nn = blockIdx.y % NSH;

    __shared__ __align__(16) float sx[T + 8];
    __shared__ __align__(16) float sw[168];
    __shared__ float red[8];
    __shared__ float result;

    const int tid = threadIdx.x;          // 128

    // ---- inline normalization (one pass: sum + sumsq) ----
    const float* xrow = x + (size_t)b * T * C + ch;   // stride C over t
    float vals[3];
    float s = 0.f, ss = 0.f;
    #pragma unroll
    for (int i = 0; i < 3; i++) {
        int t = tid + i * 128;
        float v = (t < T) ? xrow[(size_t)t * C] : 0.f;
        vals[i] = v;
        s += v;
        ss += v * v;
    }
    #pragma unroll
    for (int o = 16; o > 0; o >>= 1) {
        s  += __shfl_xor_sync(0xffffffffu, s, o);
        ss += __shfl_xor_sync(0xffffffffu, ss, o);
    }
    if ((tid & 31) == 0) { red[tid >> 5] = s; red[4 + (tid >> 5)] = ss; }
    __syncthreads();
    const float stot  = red[0] + red[1] + red[2] + red[3];
    const float sstot = red[4] + red[5] + red[6] + red[7];
    const float mu  = stot * (1.0f / (float)T);
    const float var = (sstot - (float)T * mu * mu) * (1.0f / (float)(T - 1));
    const float inv = 1.0f / (sqrtf(fmaxf(var, 0.f)) + 1e-8f);

    #pragma unroll
    for (int i = 0; i < 3; i++) {
        int t = tid + i * 128;
        if (t < T) sx[t] = (vals[i] - mu) * inv;
    }
    if (tid < 8) sx[T + tid] = 0.f;       // pad for rolling overread

    // ---- load the single shapelet row (nn, ch) of group g ----
    const float* wg;
    int L;
    switch (g) {
        case 0:  L = 34;  wg = w0; break;
        case 1:  L = 68;  wg = w1; break;
        case 2:  L = 101; wg = w2; break;
        default: L = 168; wg = w3; break;
    }
    const float* wrow = wg + (size_t)(nn * C + ch) * L;
    for (int i = tid; i < L; i += 128) sw[i] = wrow[i];
    __syncthreads();

    // ---- sliding window min-L1 ----
    switch (g) {
        case 0:  sliding_min<34, 3>(sx, sw, tid, red, &result); break;   // tw=303
        case 1:  sliding_min<68, 3>(sx, sw, tid, red, &result); break;   // tw=269
        case 2:  sliding_min<101, 2>(sx, sw, tid, red, &result); break;  // tw=236
        default: sliding_min<168, 2>(sx, sw, tid, red, &result); break;  // tw=169
    }
    __syncthreads();

    if (tid == 0) {
        const float dmin = result;
        const int idx = b * NF + g * (NSH * C) + nn * C + ch;
        d_out[OFF_DIST + idx] = dmin;
        d_out[OFF_PROB + idx] = expf(-dmin * dmin);   // EPS_GATE = 1
    }
}

// ---------------------------------------------------------------------------
// Parallel head: grid = B*OUTC + 1 blocks, 128 threads.
//   blocks 0..319 : out[b,o] = dot(probs[b,:], Wout[o,:])   (block-reduced)
//   block  320    : loss = 0.1 * mean|W_out|
// ---------------------------------------------------------------------------
__global__ __launch_bounds__(128) void head_kernel(const float* __restrict__ Wout,
                                                   float* __restrict__ d_out) {
    const int tid = threadIdx.x;          // 128
    const int blk = blockIdx.x;
    __shared__ float sred[4];

    float v = 0.f;
    if (blk < B * OUTC) {
        const int b = blk / OUTC;
        const int o = blk % OUTC;
        const float* p = d_out + OFF_PROB + b * NF;
        const float* w = Wout + o * NF;
        if (tid < NF)       v  = p[tid] * w[tid];
        if (tid + 128 < NF) v += p[tid + 128] * w[tid + 128];
    } else {
        // loss block: sum |Wout| over OUTC*NF = 1400 elements
        #pragma unroll
        for (int i = tid; i < OUTC * NF; i += 128) v += fabsf(Wout[i]);
    }

    #pragma unroll
    for (int o = 16; o > 0; o >>= 1) v += __shfl_xor_sync(0xffffffffu, v, o);
    if ((tid & 31) == 0) sred[tid >> 5] = v;
    __syncthreads();
    if (tid == 0) {
        float tot = sred[0] + sred[1] + sred[2] + sred[3];
        if (blk < B * OUTC)
            d_out[OFF_OUT + blk] = tot;
        else
            d_out[OFF_LOSS] = 0.1f * tot / (float)(OUTC * NF);
    }
}

// ---------------------------------------------------------------------------
extern "C" void kernel_launch(void* const* d_in, const int* in_sizes, int n_in,
                              void* d_out, int out_size) {
    const float* x    = (const float*)d_in[0];
    const float* w0   = (const float*)d_in[1];
    const float* w1   = (const float*)d_in[2];
    const float* w2   = (const float*)d_in[3];
    const float* w3   = (const float*)d_in[4];
    const float* Wout = (const float*)d_in[5];
    float* out = (float*)d_out;

    dim3 grid(B * C, NG * NSH);
    shapelet_kernel<<<grid, 128>>>(x, w0, w1, w2, w3, out);
    head_kernel<<<B * OUTC + 1, 128>>>(Wout, out);
}